// round 13
// baseline (speedup 1.0000x reference)
#include <cuda_runtime.h>
#include <cuda_fp16.h>
#include <cstdint>

// out = x @ (sum_k w_k W[ids_k])^T + sum_k w_k b[ids_k]
// Single-pass fp16 HMMA (validated rel_err 2.93e-4 < 1e-3).
// R13: FUSED single kernel. Chunk-ordered work-stealing prep prologue +
// per-chunk readiness counters; R9's exact 34us mainloop (best measured).
#define D_IN    1024
#define D_OUT   1024
#define M_TOTAL 4096
#define N_ADAPT 32

#define MTILE 128
#define NTILE 128
#define KC    64
#define NCH   (D_IN / KC)           // 16
#define RSTR  72                    // padded row stride (halves): 144B rows
#define XOFF  0
#define WOFF  (128 * RSTR)
#define STAGE_ELEMS (2 * 128 * RSTR)    // 18432 halves = 36864 B
#define NSTAGE 3
#define SMEM_BYTES (NSTAGE * STAGE_ELEMS * 2)   // 110592 B

// prep decomposition: per chunk 16 x-slices (256 rows) + 4 W-slices (256 rows)
#define ITEMS_PER_CHUNK 20
#define TOTAL_ITEMS (NCH * ITEMS_PER_CHUNK + 1)   // +1 bias item = 321
#define GRID_CTAS (8 * 32)

__device__ __half g_Xf[M_TOTAL * D_IN];
__device__ __half g_Wf[D_OUT * D_IN];
__device__ float  g_bmix[D_OUT];
__device__ int    g_next_work;      // zero-init; reset by last CTA
__device__ int    g_cnt[NCH];
__device__ int    g_bias_done;
__device__ int    g_finished;

// -------- PTX helpers (sm_80-era, valid for compute_103) --------------------
__device__ __forceinline__ uint32_t smem_u32(const void* p) {
    uint32_t a;
    asm("{ .reg .u64 t; cvta.to.shared.u64 t, %1; cvt.u32.u64 %0, t; }"
        : "=r"(a) : "l"(p));
    return a;
}
__device__ __forceinline__ void cp_async16(uint32_t dst, const void* src) {
    asm volatile("cp.async.cg.shared.global [%0], [%1], 16;"
                 :: "r"(dst), "l"(src) : "memory");
}
__device__ __forceinline__ void cp_commit() {
    asm volatile("cp.async.commit_group;" ::: "memory");
}
template <int N> __device__ __forceinline__ void cp_wait() {
    asm volatile("cp.async.wait_group %0;" :: "n"(N) : "memory");
}
__device__ __forceinline__ void ldsm_x4(uint32_t& r0, uint32_t& r1,
                                        uint32_t& r2, uint32_t& r3, uint32_t a) {
    asm volatile("ldmatrix.sync.aligned.m8n8.x4.shared.b16 {%0,%1,%2,%3}, [%4];"
                 : "=r"(r0), "=r"(r1), "=r"(r2), "=r"(r3) : "r"(a));
}
__device__ __forceinline__ void mma_f16(float* c, const uint32_t* a,
                                        const uint32_t* b) {
    asm volatile(
        "mma.sync.aligned.m16n8k16.row.col.f32.f16.f16.f32 "
        "{%0,%1,%2,%3}, {%4,%5,%6,%7}, {%8,%9}, {%0,%1,%2,%3};"
        : "+f"(c[0]), "+f"(c[1]), "+f"(c[2]), "+f"(c[3])
        : "r"(a[0]), "r"(a[1]), "r"(a[2]), "r"(a[3]), "r"(b[0]), "r"(b[1]));
}

// -------- ids dtype detection (JAX x64-off downcasts int64 -> int32) --------
__device__ __forceinline__ bool ids_look_i64(const void* idsptr, int K) {
    const int* p = (const int*)idsptr;
    bool odd_zero = true, even_valid = true;
    for (int k = 1; k < K; k += 2) if (p[k] != 0) odd_zero = false;
    for (int k = 0; k < K; k += 2) if (p[k] < 0 || p[k] >= N_ADAPT) even_valid = false;
    return odd_zero && even_valid;
}
__device__ __forceinline__ int load_id(const void* idsptr, int k, bool is64) {
    return is64 ? (int)((const long long*)idsptr)[k] : ((const int*)idsptr)[k];
}

// -------- prep work items ----------------------------------------------------
__device__ __forceinline__ void do_x_item(const float* __restrict__ x,
                                          int c, int s, int tid) {
    const int row  = s * 256 + (tid >> 1);
    const int colg = (tid & 1) * 32;
    const float4* src = (const float4*)(x + (size_t)row * D_IN + c * KC + colg);
    uint32_t out[16];
#pragma unroll
    for (int g = 0; g < 8; g++) {
        float4 v = __ldg(&src[g]);
        __half2 h0 = make_half2(__float2half_rn(v.x), __float2half_rn(v.y));
        __half2 h1 = make_half2(__float2half_rn(v.z), __float2half_rn(v.w));
        out[g * 2]     = *(uint32_t*)&h0;
        out[g * 2 + 1] = *(uint32_t*)&h1;
    }
    uint4* dst = (uint4*)(g_Xf + (size_t)row * D_IN + c * KC + colg);
#pragma unroll
    for (int q = 0; q < 4; q++)
        dst[q] = make_uint4(out[q*4], out[q*4+1], out[q*4+2], out[q*4+3]);
}

__device__ __forceinline__ void do_w_item(const float* __restrict__ W,
                                          const void* __restrict__ ids,
                                          const float* __restrict__ wts,
                                          int K, int c, int s, int tid) {
    const bool is64 = ids_look_i64(ids, K);
    const int row  = s * 256 + (tid >> 1);
    const int colg = (tid & 1) * 32;
    const int OD4 = D_OUT * D_IN / 4;
    const float4* W4 = (const float4*)W;
    const int base4 = row * (D_IN / 4) + (c * KC + colg) / 4;
    uint32_t out[16];
#pragma unroll
    for (int g = 0; g < 8; g++) {
        float4 acc = make_float4(0.f, 0.f, 0.f, 0.f);
        for (int k = 0; k < K; k++) {
            float w = __ldg(&wts[k]);
            long long id = load_id(ids, k, is64);
            float4 v = __ldg(&W4[id * (long long)OD4 + base4 + g]);
            acc.x += w * v.x; acc.y += w * v.y; acc.z += w * v.z; acc.w += w * v.w;
        }
        __half2 h0 = make_half2(__float2half_rn(acc.x), __float2half_rn(acc.y));
        __half2 h1 = make_half2(__float2half_rn(acc.z), __float2half_rn(acc.w));
        out[g * 2]     = *(uint32_t*)&h0;
        out[g * 2 + 1] = *(uint32_t*)&h1;
    }
    uint4* dst = (uint4*)(g_Wf + (size_t)row * D_IN + c * KC + colg);
#pragma unroll
    for (int q = 0; q < 4; q++)
        dst[q] = make_uint4(out[q*4], out[q*4+1], out[q*4+2], out[q*4+3]);
}

__device__ __forceinline__ void do_bias_item(const float* __restrict__ b,
                                             const void* __restrict__ ids,
                                             const float* __restrict__ wts,
                                             int K, int tid) {
    const bool is64 = ids_look_i64(ids, K);
    const int i = tid * 2;
    if (i < D_OUT) {
        float a0 = 0.f, a1 = 0.f;
        for (int k = 0; k < K; k++) {
            long long id = load_id(ids, k, is64);
            float w = __ldg(&wts[k]);
            a0 += w * __ldg(&b[id * (long long)D_OUT + i]);
            a1 += w * __ldg(&b[id * (long long)D_OUT + i + 1]);
        }
        g_bmix[i] = a0; g_bmix[i + 1] = a1;
    }
}

// ---------------------------------------------------------------------------
// Fused kernel: work-stealing prep prologue + R9 HMMA mainloop + epilogue.
// ---------------------------------------------------------------------------
__global__ void __launch_bounds__(512, 2)
fused_kernel(const float* __restrict__ x, const float* __restrict__ W,
             const float* __restrict__ b, const void* __restrict__ ids,
             const float* __restrict__ wts, int K, float* __restrict__ C) {
    extern __shared__ __half sm[];
    __shared__ int s_item;
    const uint32_t sbase = smem_u32(sm);

    const int tid    = threadIdx.x;
    const int lane   = tid & 31;
    const int wid    = tid >> 5;
    const int warp_m = wid & 3;
    const int warp_n = wid >> 2;
    const int m0 = blockIdx.y * MTILE;
    const int n0 = blockIdx.x * NTILE;

    // ---------------- prologue: chunk-major work-stealing prep --------------
    for (;;) {
        __syncthreads();
        if (tid == 0) s_item = atomicAdd(&g_next_work, 1);
        __syncthreads();
        const int item = s_item;
        if (item >= TOTAL_ITEMS) break;
        if (item == TOTAL_ITEMS - 1) {
            do_bias_item(b, ids, wts, K, tid);
        } else {
            const int c = item / ITEMS_PER_CHUNK;
            const int j = item % ITEMS_PER_CHUNK;
            if (j < 16) do_x_item(x, c, j, tid);
            else        do_w_item(W, ids, wts, K, c, j - 16, tid);
        }
        __threadfence();
        __syncthreads();
        if (tid == 0) {
            if (item == TOTAL_ITEMS - 1) atomicAdd(&g_bias_done, 1);
            else atomicAdd(&g_cnt[item / ITEMS_PER_CHUNK], 1);
        }
    }

    // readiness poll: all threads spin on a monotonic counter (L2-coherent)
    auto wait_chunk = [&](int c) {
        volatile int* p = &g_cnt[c];
        while (*p < ITEMS_PER_CHUNK) { __nanosleep(64); }
        __threadfence();
    };

    // ---------------- R9 mainloop (exact 34us structure) --------------------
    const int lrow = tid >> 2;
    const int lkh  = (tid & 3) * 16;
    const __half* gX = g_Xf + (size_t)(m0 + lrow) * D_IN + lkh;
    const __half* gW = g_Wf + (size_t)(n0 + lrow) * D_IN + lkh;
    const uint32_t dst = (uint32_t)(lrow * RSTR + lkh) * 2;

    auto load_stage = [&](int c) {
        const uint32_t sb = sbase + (uint32_t)(c % NSTAGE) * STAGE_ELEMS * 2;
        const size_t go = (size_t)c * KC;
#pragma unroll
        for (int j = 0; j < 2; j++) {
            const uint32_t d = dst + j * 16;
            cp_async16(sb + XOFF * 2 + d, gX + go + j * 8);
            cp_async16(sb + WOFF * 2 + d, gW + go + j * 8);
        }
    };

    const int a_row = (lane & 15);
    const int a_kof = (lane >> 4) * 8;
    const int b_row = ((lane >> 4) << 3) + (lane & 7);
    const int b_kof = ((lane >> 3) & 1) * 8;
    const uint32_t aro = (uint32_t)((warp_m * 32 + a_row) * RSTR + a_kof) * 2;
    const uint32_t bro = (uint32_t)((warp_n * 32 + b_row) * RSTR + b_kof) * 2;

    float acc[2][4][4];
#pragma unroll
    for (int i = 0; i < 2; i++)
#pragma unroll
        for (int j = 0; j < 4; j++)
#pragma unroll
            for (int q = 0; q < 4; q++) acc[i][j][q] = 0.f;

    wait_chunk(0); load_stage(0); cp_commit();
    wait_chunk(1); load_stage(1); cp_commit();

    for (int c = 0; c < NCH; c++) {
        cp_wait<NSTAGE - 2>();
        __syncthreads();

        const uint32_t sb = sbase + (uint32_t)(c % NSTAGE) * STAGE_ELEMS * 2;
#pragma unroll
        for (int ks = 0; ks < KC / 16; ks++) {
            const int k0 = ks * 16;
            uint32_t af[2][4];
#pragma unroll
            for (int mf = 0; mf < 2; mf++) {
                const uint32_t ro = aro + (uint32_t)(mf * 16 * RSTR + k0) * 2;
                ldsm_x4(af[mf][0], af[mf][1], af[mf][2], af[mf][3],
                        sb + XOFF * 2 + ro);
            }
            uint32_t bf[4][2];
#pragma unroll
            for (int ng = 0; ng < 2; ng++) {
                const uint32_t ro = bro + (uint32_t)(ng * 16 * RSTR + k0) * 2;
                uint32_t r0, r1, r2, r3;
                ldsm_x4(r0, r1, r2, r3, sb + WOFF * 2 + ro);
                bf[ng * 2][0] = r0;     bf[ng * 2][1] = r1;
                bf[ng * 2 + 1][0] = r2; bf[ng * 2 + 1][1] = r3;
            }
#pragma unroll
            for (int mf = 0; mf < 2; mf++)
#pragma unroll
                for (int nf = 0; nf < 4; nf++)
                    mma_f16(acc[mf][nf], af[mf], bf[nf]);
        }

        if (c + NSTAGE - 1 < NCH) { wait_chunk(c + NSTAGE - 1); load_stage(c + NSTAGE - 1); }
        cp_commit();
    }

    // ---------------- epilogue ----------------------------------------------
    {   // bias written this launch by another SM: poll + volatile (L1-bypass)
        volatile int* p = &g_bias_done;
        while (*p < 1) { __nanosleep(64); }
        __threadfence();
    }
    volatile const float* vb = g_bmix;
    const int g = lane >> 2;
    const int cpair = (lane & 3) * 2;
#pragma unroll
    for (int mf = 0; mf < 2; mf++) {
        const int row = m0 + warp_m * 32 + mf * 16 + g;
#pragma unroll
        for (int nf = 0; nf < 4; nf++) {
            const int col = n0 + warp_n * 32 + nf * 8 + cpair;
            const float b0 = vb[col];
            const float b1 = vb[col + 1];
            float2 v0 = make_float2(acc[mf][nf][0] + b0, acc[mf][nf][1] + b1);
            float2 v1 = make_float2(acc[mf][nf][2] + b0, acc[mf][nf][3] + b1);
            *(float2*)(C + (size_t)row * D_OUT + col) = v0;
            *(float2*)(C + (size_t)(row + 8) * D_OUT + col) = v1;
        }
    }

    // ---------------- reset counters for next graph replay ------------------
    __syncthreads();
    if (tid == 0) {
        __threadfence();
        const int f = atomicAdd(&g_finished, 1);
        if (f == GRID_CTAS - 1) {
            for (int c = 0; c < NCH; c++) g_cnt[c] = 0;
            g_next_work = 0;
            g_bias_done = 0;
            g_finished  = 0;
            __threadfence();
        }
    }
}

// ---------------------------------------------------------------------------
extern "C" void kernel_launch(void* const* d_in, const int* in_sizes, int n_in,
                              void* d_out, int out_size) {
    const float* x   = (const float*)d_in[0];
    const float* W   = (const float*)d_in[1];
    const float* b   = (const float*)d_in[2];
    const void*  ids = d_in[3];
    const float* wts = (const float*)d_in[4];
    const int K = in_sizes[3];

    cudaFuncSetAttribute(fused_kernel,
                         cudaFuncAttributeMaxDynamicSharedMemorySize, SMEM_BYTES);

    dim3 grid(D_OUT / NTILE, M_TOTAL / MTILE);  // (8, 32) = 256 CTAs
    fused_kernel<<<grid, 512, SMEM_BYTES>>>(x, W, b, ids, wts, K, (float*)d_out);
}

// round 14
// speedup vs baseline: 2.2260x; 2.2260x over previous
#include <cuda_runtime.h>
#include <cuda_fp16.h>
#include <cstdint>

// out = x @ (sum_k w_k W[ids_k])^T + sum_k w_k b[ids_k]
// Single-pass fp16 HMMA (validated rel_err 2.93e-4 < 1e-3).
// R14: fused kernel, take 2. R9's exact mainloop + statically-owned,
// time-distributed prep (no work-stealing), tid0-only polling (no LDG storm).
#define D_IN    1024
#define D_OUT   1024
#define M_TOTAL 4096
#define N_ADAPT 32

#define MTILE 128
#define NTILE 128
#define KC    64
#define NCH   (D_IN / KC)           // 16
#define RSTR  72
#define XOFF  0
#define WOFF  (128 * RSTR)
#define STAGE_ELEMS (2 * 128 * RSTR)
#define NSTAGE 3
#define SMEM_BYTES (NSTAGE * STAGE_ELEMS * 2)   // 110592 B
#define ITEMS_PER_CHUNK 32          // 16 x-items + 16 W-items
#define GRID_CTAS 256

__device__ __half g_Xf[M_TOTAL * D_IN];
__device__ __half g_Wf[D_OUT * D_IN];
__device__ float  g_bmix[D_OUT];
__device__ int    g_cnt[NCH];       // zero-init; reset by last CTA
__device__ int    g_bias_done;
__device__ int    g_finished;

// -------- PTX helpers --------------------------------------------------------
__device__ __forceinline__ uint32_t smem_u32(const void* p) {
    uint32_t a;
    asm("{ .reg .u64 t; cvta.to.shared.u64 t, %1; cvt.u32.u64 %0, t; }"
        : "=r"(a) : "l"(p));
    return a;
}
__device__ __forceinline__ void cp_async16(uint32_t dst, const void* src) {
    asm volatile("cp.async.cg.shared.global [%0], [%1], 16;"
                 :: "r"(dst), "l"(src) : "memory");
}
__device__ __forceinline__ void cp_commit() {
    asm volatile("cp.async.commit_group;" ::: "memory");
}
template <int N> __device__ __forceinline__ void cp_wait() {
    asm volatile("cp.async.wait_group %0;" :: "n"(N) : "memory");
}
__device__ __forceinline__ void ldsm_x4(uint32_t& r0, uint32_t& r1,
                                        uint32_t& r2, uint32_t& r3, uint32_t a) {
    asm volatile("ldmatrix.sync.aligned.m8n8.x4.shared.b16 {%0,%1,%2,%3}, [%4];"
                 : "=r"(r0), "=r"(r1), "=r"(r2), "=r"(r3) : "r"(a));
}
__device__ __forceinline__ void mma_f16(float* c, const uint32_t* a,
                                        const uint32_t* b) {
    asm volatile(
        "mma.sync.aligned.m16n8k16.row.col.f32.f16.f16.f32 "
        "{%0,%1,%2,%3}, {%4,%5,%6,%7}, {%8,%9}, {%0,%1,%2,%3};"
        : "+f"(c[0]), "+f"(c[1]), "+f"(c[2]), "+f"(c[3])
        : "r"(a[0]), "r"(a[1]), "r"(a[2]), "r"(a[3]), "r"(b[0]), "r"(b[1]));
}

// -------- ids dtype detection ------------------------------------------------
__device__ __forceinline__ bool ids_look_i64(const void* idsptr, int K) {
    const int* p = (const int*)idsptr;
    bool odd_zero = true, even_valid = true;
    for (int k = 1; k < K; k += 2) if (p[k] != 0) odd_zero = false;
    for (int k = 0; k < K; k += 2) if (p[k] < 0 || p[k] >= N_ADAPT) even_valid = false;
    return odd_zero && even_valid;
}
__device__ __forceinline__ int load_id(const void* idsptr, int k, bool is64) {
    return is64 ? (int)((const long long*)idsptr)[k] : ((const int*)idsptr)[k];
}

// -------- prep items (__noinline__ keeps mainloop register budget clean) -----
__device__ __noinline__ void do_x_item(const float* __restrict__ x,
                                       int c, int item, int tid) {
    const int row  = item * 256 + (tid >> 1);
    const int col0 = c * KC + (tid & 1) * 32;
    const float4* src = (const float4*)(x + (size_t)row * D_IN + col0);
    uint32_t out[16];
#pragma unroll
    for (int g = 0; g < 8; g++) {
        float4 v = __ldg(&src[g]);
        __half2 h0 = make_half2(__float2half_rn(v.x), __float2half_rn(v.y));
        __half2 h1 = make_half2(__float2half_rn(v.z), __float2half_rn(v.w));
        out[g * 2]     = *(uint32_t*)&h0;
        out[g * 2 + 1] = *(uint32_t*)&h1;
    }
    uint4* dst = (uint4*)(g_Xf + (size_t)row * D_IN + col0);
#pragma unroll
    for (int q = 0; q < 4; q++)
        dst[q] = make_uint4(out[q*4], out[q*4+1], out[q*4+2], out[q*4+3]);
}

__device__ __noinline__ void do_w_item(const float* __restrict__ W,
                                       const void* __restrict__ ids,
                                       const float* __restrict__ wts,
                                       int K, int c, int item, int tid) {
    const bool is64 = ids_look_i64(ids, K);
    const int row  = item * 64 + (tid >> 3);
    const int col0 = c * KC + (tid & 7) * 8;
    const int ODE = D_OUT * D_IN;
    float a0 = 0.f, a1 = 0.f, a2 = 0.f, a3 = 0.f;
    float a4 = 0.f, a5 = 0.f, a6 = 0.f, a7 = 0.f;
    for (int k = 0; k < K; k++) {
        const float w = __ldg(&wts[k]);
        const long long id = load_id(ids, k, is64);
        const float4* src = (const float4*)(W + id * (long long)ODE
                                              + (size_t)row * D_IN + col0);
        float4 v0 = __ldg(&src[0]);
        float4 v1 = __ldg(&src[1]);
        a0 += w * v0.x; a1 += w * v0.y; a2 += w * v0.z; a3 += w * v0.w;
        a4 += w * v1.x; a5 += w * v1.y; a6 += w * v1.z; a7 += w * v1.w;
    }
    __half2 h0 = make_half2(__float2half_rn(a0), __float2half_rn(a1));
    __half2 h1 = make_half2(__float2half_rn(a2), __float2half_rn(a3));
    __half2 h2 = make_half2(__float2half_rn(a4), __float2half_rn(a5));
    __half2 h3 = make_half2(__float2half_rn(a6), __float2half_rn(a7));
    *(uint4*)(g_Wf + (size_t)row * D_IN + col0) =
        make_uint4(*(uint32_t*)&h0, *(uint32_t*)&h1,
                   *(uint32_t*)&h2, *(uint32_t*)&h3);
}

__device__ __noinline__ void do_bias(const float* __restrict__ b,
                                     const void* __restrict__ ids,
                                     const float* __restrict__ wts,
                                     int K, int tid) {
    const bool is64 = ids_look_i64(ids, K);
    const int i = tid * 2;
    float a0 = 0.f, a1 = 0.f;
    for (int k = 0; k < K; k++) {
        const long long id = load_id(ids, k, is64);
        const float w = __ldg(&wts[k]);
        a0 += w * __ldg(&b[id * (long long)D_OUT + i]);
        a1 += w * __ldg(&b[id * (long long)D_OUT + i + 1]);
    }
    g_bmix[i] = a0; g_bmix[i + 1] = a1;
}

// ---------------------------------------------------------------------------
__global__ void __launch_bounds__(512, 2)
fused_kernel(const float* __restrict__ x, const float* __restrict__ W,
             const float* __restrict__ b, const void* __restrict__ ids,
             const float* __restrict__ wts, int K, float* __restrict__ C) {
    extern __shared__ __half sm[];
    const uint32_t sbase = smem_u32(sm);

    const int tid    = threadIdx.x;
    const int lane   = tid & 31;
    const int wid    = tid >> 5;
    const int warp_m = wid & 3;
    const int warp_n = wid >> 2;
    const int m0 = blockIdx.y * MTILE;
    const int n0 = blockIdx.x * NTILE;

    // static prep ownership
    const int L    = blockIdx.y * 8 + blockIdx.x;   // 0..255
    const int c1   = L >> 5;                        // 0..7
    const int c2   = c1 + 8;                        // 8..15
    const int item = L & 31;                        // 0..31

    auto do_item = [&](int c) {
        if (item < 16) do_x_item(x, c, item, tid);
        else           do_w_item(W, ids, wts, K, c, item - 16, tid);
        __threadfence();
        __syncthreads();
        if (tid == 0) atomicAdd(&g_cnt[c], 1);
    };
    auto poll_chunk = [&](int c) {   // call from tid==0 only
        volatile int* p = &g_cnt[c];
        while (*p < ITEMS_PER_CHUNK) { __nanosleep(128); }
    };

    // ---------------- prologue: chunks 0..3 + bias --------------------------
    if (c1 < 4) do_item(c1);
    if (L == 128) {
        do_bias(b, ids, wts, K, tid);
        __threadfence();
        __syncthreads();
        if (tid == 0) atomicAdd(&g_bias_done, 1);
    }

    // ---------------- R9 mainloop with readiness gating ----------------------
    const int lrow = tid >> 2;
    const int lkh  = (tid & 3) * 16;
    const __half* gX = g_Xf + (size_t)(m0 + lrow) * D_IN + lkh;
    const __half* gW = g_Wf + (size_t)(n0 + lrow) * D_IN + lkh;
    const uint32_t dst = (uint32_t)(lrow * RSTR + lkh) * 2;

    auto load_stage = [&](int c) {
        const uint32_t sb = sbase + (uint32_t)(c % NSTAGE) * STAGE_ELEMS * 2;
        const size_t go = (size_t)c * KC;
#pragma unroll
        for (int j = 0; j < 2; j++) {
            const uint32_t d = dst + j * 16;
            cp_async16(sb + XOFF * 2 + d, gX + go + j * 8);
            cp_async16(sb + WOFF * 2 + d, gW + go + j * 8);
        }
    };

    const int a_row = (lane & 15);
    const int a_kof = (lane >> 4) * 8;
    const int b_row = ((lane >> 4) << 3) + (lane & 7);
    const int b_kof = ((lane >> 3) & 1) * 8;
    const uint32_t aro = (uint32_t)((warp_m * 32 + a_row) * RSTR + a_kof) * 2;
    const uint32_t bro = (uint32_t)((warp_n * 32 + b_row) * RSTR + b_kof) * 2;

    float acc[2][4][4];
#pragma unroll
    for (int i = 0; i < 2; i++)
#pragma unroll
        for (int j = 0; j < 4; j++)
#pragma unroll
            for (int q = 0; q < 4; q++) acc[i][j][q] = 0.f;

    if (tid == 0) { poll_chunk(0); poll_chunk(1); }
    __syncthreads();
    load_stage(0); cp_commit();
    load_stage(1); cp_commit();

    for (int c = 0; c < NCH; c++) {
        cp_wait<NSTAGE - 2>();
        if (tid == 0 && c + 2 < NCH) poll_chunk(c + 2);   // gate next load
        __syncthreads();

        const uint32_t sb = sbase + (uint32_t)(c % NSTAGE) * STAGE_ELEMS * 2;
#pragma unroll
        for (int ks = 0; ks < KC / 16; ks++) {
            const int k0 = ks * 16;
            uint32_t af[2][4];
#pragma unroll
            for (int mf = 0; mf < 2; mf++) {
                const uint32_t ro = aro + (uint32_t)(mf * 16 * RSTR + k0) * 2;
                ldsm_x4(af[mf][0], af[mf][1], af[mf][2], af[mf][3],
                        sb + XOFF * 2 + ro);
            }
            uint32_t bf[4][2];
#pragma unroll
            for (int ng = 0; ng < 2; ng++) {
                const uint32_t ro = bro + (uint32_t)(ng * 16 * RSTR + k0) * 2;
                uint32_t r0, r1, r2, r3;
                ldsm_x4(r0, r1, r2, r3, sb + WOFF * 2 + ro);
                bf[ng * 2][0] = r0;     bf[ng * 2][1] = r1;
                bf[ng * 2 + 1][0] = r2; bf[ng * 2 + 1][1] = r3;
            }
#pragma unroll
            for (int mf = 0; mf < 2; mf++)
#pragma unroll
                for (int nf = 0; nf < 4; nf++)
                    mma_f16(acc[mf][nf], af[mf], bf[nf]);
        }

        if (c + NSTAGE - 1 < NCH) load_stage(c + NSTAGE - 1);
        cp_commit();

        // time-distributed prep: owners of chunk c+4 run now (2-iter margin)
        if (c1 >= 4 && c1 == c + 4) do_item(c1);
        if (c2 == c + 4)            do_item(c2);
    }

    // ---------------- epilogue ----------------------------------------------
    if (tid == 0) {
        volatile int* p = &g_bias_done;
        while (*p < 1) { __nanosleep(128); }
    }
    __syncthreads();

    const int g = lane >> 2;
    const int cpair = (lane & 3) * 2;
#pragma unroll
    for (int mf = 0; mf < 2; mf++) {
        const int row = m0 + warp_m * 32 + mf * 16 + g;
#pragma unroll
        for (int nf = 0; nf < 4; nf++) {
            const int col = n0 + warp_n * 32 + nf * 8 + cpair;
            const float b0 = __ldg(&g_bmix[col]);
            const float b1 = __ldg(&g_bmix[col + 1]);
            float2 v0 = make_float2(acc[mf][nf][0] + b0, acc[mf][nf][1] + b1);
            float2 v1 = make_float2(acc[mf][nf][2] + b0, acc[mf][nf][3] + b1);
            *(float2*)(C + (size_t)row * D_OUT + col) = v0;
            *(float2*)(C + (size_t)(row + 8) * D_OUT + col) = v1;
        }
    }

    // ---------------- counter reset for graph replays ------------------------
    __syncthreads();
    if (tid == 0) {
        __threadfence();
        if (atomicAdd(&g_finished, 1) == GRID_CTAS - 1) {
            for (int c = 0; c < NCH; c++) g_cnt[c] = 0;
            g_bias_done = 0;
            g_finished  = 0;
            __threadfence();
        }
    }
}

// ---------------------------------------------------------------------------
extern "C" void kernel_launch(void* const* d_in, const int* in_sizes, int n_in,
                              void* d_out, int out_size) {
    const float* x   = (const float*)d_in[0];
    const float* W   = (const float*)d_in[1];
    const float* b   = (const float*)d_in[2];
    const void*  ids = d_in[3];
    const float* wts = (const float*)d_in[4];
    const int K = in_sizes[3];

    cudaFuncSetAttribute(fused_kernel,
                         cudaFuncAttributeMaxDynamicSharedMemorySize, SMEM_BYTES);

    dim3 grid(D_OUT / NTILE, M_TOTAL / MTILE);  // (8, 32) = 256 CTAs
    fused_kernel<<<grid, 512, SMEM_BYTES>>>(x, W, b, ids, wts, K, (float*)d_out);
}

// round 15
// speedup vs baseline: 4.3164x; 1.9390x over previous
#include <cuda_runtime.h>
#include <cuda_fp16.h>
#include <cstdint>

// out = x @ (sum_k w_k W[ids_k])^T + sum_k w_k b[ids_k]
// Single-pass fp16 HMMA (validated rel_err 2.93e-4 < 1e-3).
// R15: revert to R9 (best measured: GEMM 34us) + fatter prep blocks
// (x-convert at MLP=4, 4x fewer blocks). Fusion abandoned after 2 failures.
#define D_IN    1024
#define D_OUT   1024
#define M_TOTAL 4096
#define N_ADAPT 32

__device__ __half g_Xf[M_TOTAL * D_IN];
__device__ __half g_Wf[D_OUT * D_IN];
__device__ float  g_bmix[D_OUT];

// -------- PTX helpers (sm_80-era, valid for compute_103) --------------------
__device__ __forceinline__ uint32_t smem_u32(const void* p) {
    uint32_t a;
    asm("{ .reg .u64 t; cvta.to.shared.u64 t, %1; cvt.u32.u64 %0, t; }"
        : "=r"(a) : "l"(p));
    return a;
}
__device__ __forceinline__ void cp_async16(uint32_t dst, const void* src) {
    asm volatile("cp.async.cg.shared.global [%0], [%1], 16;"
                 :: "r"(dst), "l"(src) : "memory");
}
__device__ __forceinline__ void cp_commit() {
    asm volatile("cp.async.commit_group;" ::: "memory");
}
template <int N> __device__ __forceinline__ void cp_wait() {
    asm volatile("cp.async.wait_group %0;" :: "n"(N) : "memory");
}
__device__ __forceinline__ void ldsm_x4(uint32_t& r0, uint32_t& r1,
                                        uint32_t& r2, uint32_t& r3, uint32_t a) {
    asm volatile("ldmatrix.sync.aligned.m8n8.x4.shared.b16 {%0,%1,%2,%3}, [%4];"
                 : "=r"(r0), "=r"(r1), "=r"(r2), "=r"(r3) : "r"(a));
}
__device__ __forceinline__ void mma_f16(float* c, const uint32_t* a,
                                        const uint32_t* b) {
    asm volatile(
        "mma.sync.aligned.m16n8k16.row.col.f32.f16.f16.f32 "
        "{%0,%1,%2,%3}, {%4,%5,%6,%7}, {%8,%9}, {%0,%1,%2,%3};"
        : "+f"(c[0]), "+f"(c[1]), "+f"(c[2]), "+f"(c[3])
        : "r"(a[0]), "r"(a[1]), "r"(a[2]), "r"(a[3]), "r"(b[0]), "r"(b[1]));
}

// -------- ids dtype detection (JAX x64-off downcasts int64 -> int32) --------
__device__ __forceinline__ bool ids_look_i64(const void* idsptr, int K) {
    const int* p = (const int*)idsptr;
    bool odd_zero = true, even_valid = true;
    for (int k = 1; k < K; k += 2) if (p[k] != 0) odd_zero = false;
    for (int k = 0; k < K; k += 2) if (p[k] < 0 || p[k] >= N_ADAPT) even_valid = false;
    return odd_zero && even_valid;
}
__device__ __forceinline__ int load_id(const void* idsptr, int k, bool is64) {
    return is64 ? (int)((const long long*)idsptr)[k] : ((const int*)idsptr)[k];
}

// ---------------------------------------------------------------------------
// Fused prep: blocks [0,1024): x->fp16 (4 float4/thread, MLP=4);
//             [1024,2048): Wmix->fp16 ; 2048: bias
// ---------------------------------------------------------------------------
#define XBLKS 1024
#define WBLKS 1024
__global__ void prep_all_kernel(const float* __restrict__ x,
                                const float* __restrict__ W,
                                const float* __restrict__ b,
                                const void* __restrict__ ids,
                                const float* __restrict__ wts, int K) {
    const int bid = blockIdx.x;
    if (bid < XBLKS) {
        // 1M float4 total; each block covers 1024 consecutive float4s,
        // each thread 4 (stride 256) -> MLP=4 independent loads.
        const int base = bid * 1024 + threadIdx.x;
        float4 v0 = __ldg(&((const float4*)x)[base]);
        float4 v1 = __ldg(&((const float4*)x)[base + 256]);
        float4 v2 = __ldg(&((const float4*)x)[base + 512]);
        float4 v3 = __ldg(&((const float4*)x)[base + 768]);
        float4 vv[4] = {v0, v1, v2, v3};
#pragma unroll
        for (int q = 0; q < 4; q++) {
            const int i = base + q * 256;
            __half2 p0 = make_half2(__float2half_rn(vv[q].x), __float2half_rn(vv[q].y));
            __half2 p1 = make_half2(__float2half_rn(vv[q].z), __float2half_rn(vv[q].w));
            ((__half2*)g_Xf)[i * 2]     = p0;
            ((__half2*)g_Xf)[i * 2 + 1] = p1;
        }
    } else if (bid < XBLKS + WBLKS) {
        const bool is64 = ids_look_i64(ids, K);
        const int i = (bid - XBLKS) * 256 + threadIdx.x;  // float4 index into Wmix
        const int OD4 = D_OUT * D_IN / 4;
        const float4* W4 = (const float4*)W;
        float4 acc = make_float4(0.f, 0.f, 0.f, 0.f);
        for (int k = 0; k < K; k++) {
            float w = __ldg(&wts[k]);
            long long id = load_id(ids, k, is64);
            float4 v = __ldg(&W4[id * (long long)OD4 + i]);
            acc.x += w * v.x; acc.y += w * v.y; acc.z += w * v.z; acc.w += w * v.w;
        }
        __half2 p0 = make_half2(__float2half_rn(acc.x), __float2half_rn(acc.y));
        __half2 p1 = make_half2(__float2half_rn(acc.z), __float2half_rn(acc.w));
        ((__half2*)g_Wf)[i * 2]     = p0;
        ((__half2*)g_Wf)[i * 2 + 1] = p1;
    } else {
        const bool is64 = ids_look_i64(ids, K);
        for (int i = threadIdx.x; i < D_OUT; i += 256) {
            float acc = 0.f;
            for (int k = 0; k < K; k++) {
                long long id = load_id(ids, k, is64);
                acc += __ldg(&wts[k]) * __ldg(&b[id * (long long)D_OUT + i]);
            }
            g_bmix[i] = acc;
        }
    }
}

// ---------------------------------------------------------------------------
// GEMM: C[m,n] = sum_d x[m,d] Wmix[n,d] + bmix[n]   (R9 verbatim — 34us)
// CTA 128x128, 16 warps (4Mx4N), warp tile 32x32, K-chunk 64, 3-stage cp.async.
// 512 threads, 64 regs -> 2 CTA/SM = 32 warps/SM.
// ---------------------------------------------------------------------------
#define MTILE 128
#define NTILE 128
#define KC    64
#define NCH   (D_IN / KC)           // 16
#define RSTR  72                    // padded row stride (halves): 144B rows
#define XOFF  0
#define WOFF  (128 * RSTR)
#define STAGE_ELEMS (2 * 128 * RSTR)    // 18432 halves = 36864 B
#define NSTAGE 3
#define SMEM_BYTES (NSTAGE * STAGE_ELEMS * 2)   // 110592 B

__global__ void __launch_bounds__(512, 2)
gemm_mma_kernel(float* __restrict__ C) {
    extern __shared__ __half sm[];
    const uint32_t sbase = smem_u32(sm);

    const int tid    = threadIdx.x;
    const int lane   = tid & 31;
    const int wid    = tid >> 5;        // 0..15
    const int warp_m = wid & 3;         // 4 warps in M (32 rows each)
    const int warp_n = wid >> 2;        // 4 warps in N (32 cols each)
    const int m0 = blockIdx.y * MTILE;
    const int n0 = blockIdx.x * NTILE;

    // global->smem: 4 threads per 128B row; each thread 2 x 16B per array.
    const int lrow = tid >> 2;              // 0..127
    const int lkh  = (tid & 3) * 16;        // half offset: 0,16,32,48
    const __half* gX = g_Xf + (size_t)(m0 + lrow) * D_IN + lkh;
    const __half* gW = g_Wf + (size_t)(n0 + lrow) * D_IN + lkh;
    const uint32_t dst = (uint32_t)(lrow * RSTR + lkh) * 2;

    auto load_stage = [&](int c) {
        const uint32_t sb = sbase + (uint32_t)(c % NSTAGE) * STAGE_ELEMS * 2;
        const size_t go = (size_t)c * KC;
#pragma unroll
        for (int j = 0; j < 2; j++) {
            const uint32_t d = dst + j * 16;
            cp_async16(sb + XOFF * 2 + d, gX + go + j * 8);
            cp_async16(sb + WOFF * 2 + d, gW + go + j * 8);
        }
    };

    // ldmatrix lane mapping (validated layout R4-R9)
    const int a_row = (lane & 15);
    const int a_kof = (lane >> 4) * 8;
    const int b_row = ((lane >> 4) << 3) + (lane & 7);
    const int b_kof = ((lane >> 3) & 1) * 8;

    const uint32_t aro = (uint32_t)((warp_m * 32 + a_row) * RSTR + a_kof) * 2;
    const uint32_t bro = (uint32_t)((warp_n * 32 + b_row) * RSTR + b_kof) * 2;

    float acc[2][4][4];
#pragma unroll
    for (int i = 0; i < 2; i++)
#pragma unroll
        for (int j = 0; j < 4; j++)
#pragma unroll
            for (int q = 0; q < 4; q++) acc[i][j][q] = 0.f;

    load_stage(0); cp_commit();
    load_stage(1); cp_commit();

    for (int c = 0; c < NCH; c++) {
        cp_wait<NSTAGE - 2>();      // stage c resident
        __syncthreads();

        const uint32_t sb = sbase + (uint32_t)(c % NSTAGE) * STAGE_ELEMS * 2;
#pragma unroll
        for (int ks = 0; ks < KC / 16; ks++) {
            const int k0 = ks * 16;
            uint32_t af[2][4];
#pragma unroll
            for (int mf = 0; mf < 2; mf++) {
                const uint32_t ro = aro + (uint32_t)(mf * 16 * RSTR + k0) * 2;
                ldsm_x4(af[mf][0], af[mf][1], af[mf][2], af[mf][3],
                        sb + XOFF * 2 + ro);
            }
            uint32_t bf[4][2];
#pragma unroll
            for (int ng = 0; ng < 2; ng++) {
                const uint32_t ro = bro + (uint32_t)(ng * 16 * RSTR + k0) * 2;
                uint32_t r0, r1, r2, r3;
                ldsm_x4(r0, r1, r2, r3, sb + WOFF * 2 + ro);
                bf[ng * 2][0] = r0;     bf[ng * 2][1] = r1;
                bf[ng * 2 + 1][0] = r2; bf[ng * 2 + 1][1] = r3;
            }
#pragma unroll
            for (int mf = 0; mf < 2; mf++)
#pragma unroll
                for (int nf = 0; nf < 4; nf++)
                    mma_f16(acc[mf][nf], af[mf], bf[nf]);
        }

        if (c + NSTAGE - 1 < NCH) load_stage(c + NSTAGE - 1);
        cp_commit();    // unconditional: empty tail groups keep wait<> sound
    }

    // epilogue: add bias, store float2 pairs
    const int g = lane >> 2;
    const int cpair = (lane & 3) * 2;
#pragma unroll
    for (int mf = 0; mf < 2; mf++) {
        const int row = m0 + warp_m * 32 + mf * 16 + g;
#pragma unroll
        for (int nf = 0; nf < 4; nf++) {
            const int col = n0 + warp_n * 32 + nf * 8 + cpair;
            const float b0 = __ldg(&g_bmix[col]);
            const float b1 = __ldg(&g_bmix[col + 1]);
            float2 v0 = make_float2(acc[mf][nf][0] + b0, acc[mf][nf][1] + b1);
            float2 v1 = make_float2(acc[mf][nf][2] + b0, acc[mf][nf][3] + b1);
            *(float2*)(C + (size_t)row * D_OUT + col) = v0;
            *(float2*)(C + (size_t)(row + 8) * D_OUT + col) = v1;
        }
    }
}

// ---------------------------------------------------------------------------
extern "C" void kernel_launch(void* const* d_in, const int* in_sizes, int n_in,
                              void* d_out, int out_size) {
    const float* x   = (const float*)d_in[0];
    const float* W   = (const float*)d_in[1];
    const float* b   = (const float*)d_in[2];
    const void*  ids = d_in[3];
    const float* wts = (const float*)d_in[4];
    const int K = in_sizes[3];

    cudaFuncSetAttribute(gemm_mma_kernel,
                         cudaFuncAttributeMaxDynamicSharedMemorySize, SMEM_BYTES);

    prep_all_kernel<<<XBLKS + WBLKS + 1, 256>>>(x, W, b, ids, wts, K);

    dim3 grid(D_OUT / NTILE, M_TOTAL / MTILE);  // (8, 32) = 256 CTAs
    gemm_mma_kernel<<<grid, 512, SMEM_BYTES>>>((float*)d_out);
}